// round 7
// baseline (speedup 1.0000x reference)
#include <cuda_runtime.h>
#include <cuda_bf16.h>

// NSLoss fused single-kernel.
// loss = -(1/n) * sum_i [ log_sigmoid(<emb_i, W[label_i]>)
//                         + sum_k log_sigmoid(-<emb_i, W[negs_ik]>) ]
// Inputs (metadata order): y_hat f32[N] (unused), emb f32[N,128],
// weights f32[1e6,128], label i32[N], negs i32[N,10]. Output: f32 scalar.
//
// Warp-per-row. Phase-ordered for MLP=12 (all 11 gather rows + emb in flight),
// butterfly reduce interleaved across all 11 dots, single log-sigmoid per lane.
// Last arriving block finalizes and resets state (graph-replayable).

#define D 128
#define NUM_SAMPLED 10
#define NROWS (NUM_SAMPLED + 1)
#define THREADS 256
#define WARPS_PER_BLOCK (THREADS / 32)
#define NUM_NODES 1000000

__device__ double g_acc = 0.0;
__device__ unsigned int g_arrived = 0;

__device__ __forceinline__ float log_sigmoid_f(float x) {
    return fminf(x, 0.0f) - log1pf(__expf(-fabsf(x)));
}

__global__ __launch_bounds__(THREADS, 2)
void nsloss_fused_kernel(const float* __restrict__ emb,
                         const float* __restrict__ weights,
                         const int* __restrict__ label,
                         const int* __restrict__ negs,
                         float* __restrict__ out,
                         int n) {
    const int lane = threadIdx.x & 31;
    const int warp_in_blk = threadIdx.x >> 5;
    const int i = blockIdx.x * WARPS_PER_BLOCK + warp_in_blk;

    float warp_partial = 0.0f;

    if (i < n) {
        // ---- Phase 1: indices (one small coalesced read) ----
        int my_idx = 0;
        if (lane == 0)                my_idx = label[i];
        else if (lane <= NUM_SAMPLED) my_idx = negs[i * NUM_SAMPLED + (lane - 1)];
        my_idx = min(max(my_idx, 0), NUM_NODES - 1);

        // ---- Phase 2: ALL loads issued back-to-back (MLP = 12) ----
        const float4 e = reinterpret_cast<const float4*>(emb + (size_t)i * D)[lane];
        float4 w[NROWS];
        #pragma unroll
        for (int k = 0; k < NROWS; ++k) {
            int row = __shfl_sync(0xffffffffu, my_idx, k);
            w[k] = reinterpret_cast<const float4*>(weights + (size_t)row * D)[lane];
        }

        // ---- Phase 3: per-lane partial dots (independent FFMAs) ----
        float d[NROWS];
        #pragma unroll
        for (int k = 0; k < NROWS; ++k)
            d[k] = e.x * w[k].x + e.y * w[k].y + e.z * w[k].z + e.w * w[k].w;

        // ---- Phase 4: butterfly reduce, interleaved across all 11 dots ----
        // Each stage: 11 independent SHFLs (ILP hides the 26-cycle latency).
        #pragma unroll
        for (int off = 16; off > 0; off >>= 1) {
            #pragma unroll
            for (int k = 0; k < NROWS; ++k)
                d[k] += __shfl_xor_sync(0xffffffffu, d[k], off);
        }

        // ---- Phase 5: lane k handles sample k (one MUFU pair per lane) ----
        // All lanes hold every dot; select with an unrolled FSEL chain
        // (no dynamic register indexing -> no local-memory spill).
        float mydot = 0.0f;
        #pragma unroll
        for (int k = 0; k < NROWS; ++k)
            if (lane == k) mydot = d[k];
        float contrib = 0.0f;
        if (lane < NROWS) {
            float s = (lane == 0) ? mydot : -mydot;  // positive vs negatives
            contrib = log_sigmoid_f(s);
        }

        // ---- Phase 6: sum the 11 contributions across the warp ----
        #pragma unroll
        for (int off = 16; off > 0; off >>= 1)
            contrib += __shfl_xor_sync(0xffffffffu, contrib, off);
        warp_partial = contrib;   // lane-uniform
    }

    // Block reduce + global accumulate.
    __shared__ float warp_sums[WARPS_PER_BLOCK];
    __shared__ bool is_last;
    if (lane == 0) warp_sums[warp_in_blk] = warp_partial;
    __syncthreads();

    if (threadIdx.x == 0) {
        float s = 0.0f;
        #pragma unroll
        for (int wi = 0; wi < WARPS_PER_BLOCK; ++wi) s += warp_sums[wi];
        atomicAdd(&g_acc, (double)s);
        __threadfence();
        unsigned int prev = atomicAdd(&g_arrived, 1u);
        is_last = (prev == gridDim.x - 1);
    }
    __syncthreads();

    // Last block finalizes: write output, reset state for next graph replay.
    if (is_last && threadIdx.x == 0) {
        double total = g_acc;
        out[0] = (float)(-total / (double)n);
        g_acc = 0.0;
        g_arrived = 0u;
        __threadfence();
    }
}

extern "C" void kernel_launch(void* const* d_in, const int* in_sizes, int n_in,
                              void* d_out, int out_size) {
    const float* emb     = (const float*)d_in[1];
    const float* weights = (const float*)d_in[2];
    const int*   label   = (const int*)d_in[3];
    const int*   negs    = (const int*)d_in[4];
    float* out = (float*)d_out;

    const int n = in_sizes[0];              // N from y_hat length
    const int blocks = (n + WARPS_PER_BLOCK - 1) / WARPS_PER_BLOCK;

    nsloss_fused_kernel<<<blocks, THREADS>>>(emb, weights, label, negs, out, n);
}